// round 3
// baseline (speedup 1.0000x reference)
#include <cuda_runtime.h>
#include <math.h>

#define Bn 512
#define Hn 1024
#define Sn 1024
#define Dn 128
#define Kn 32

// Output layout: [read (B*D)] [new_memory (B*S*D)] [weights (B*S)]
#define READ_OFF 0
#define MEM_OFF  (Bn*Dn)
#define W_OFF    (Bn*Dn + (size_t)Bn*Sn*Dn)

// Scratch (no allocation allowed -> device globals)
__device__ float4 g_query[Bn * (Dn/4)];   // [B][32] float4
__device__ float4 g_value[Bn * (Dn/4)];
__device__ float  g_logits[Bn * Sn];
__device__ float  g_gate[Bn];
__device__ int    g_ti[Bn * Kn];
__device__ float  g_tw[Bn * Kn];

// ---------------------------------------------------------------------------
// K1: query = latent @ Wq + bq ; value = latent @ Wv + bv
// 8 batches per block, 256 threads; thread owns d-quad x 8 batches.
// ---------------------------------------------------------------------------
__global__ __launch_bounds__(256, 2)
void qv_kernel(const float* __restrict__ latent,
               const float* __restrict__ Wq, const float* __restrict__ bq,
               const float* __restrict__ Wv, const float* __restrict__ bv)
{
    __shared__ float4 smem[8 * 256];   // 32 KB: latent tile, then reduction overlay

    const int b0 = blockIdx.x * 8;
    const float4* W4    = (const float4*)(blockIdx.y ? Wv : Wq);
    const float4* bias4 = (const float4*)(blockIdx.y ? bv : bq);
    float4*       out4  = blockIdx.y ? g_value : g_query;

    const int tid = threadIdx.x;
    const int dq  = tid & 31;
    const int hs  = tid >> 5;

    {
        const float4* src = (const float4*)(latent + (size_t)b0 * Hn);
        #pragma unroll
        for (int i = 0; i < 8; i++) smem[tid + i * 256] = src[tid + i * 256];
    }
    __syncthreads();

    float4 acc[8];
    #pragma unroll
    for (int j = 0; j < 8; j++) acc[j] = make_float4(0.f, 0.f, 0.f, 0.f);

    const int hbase = hs * 128;
    #pragma unroll 4
    for (int c = 0; c < 32; c++) {
        const int h0 = hbase + c * 4;
        float4 w0 = W4[(size_t)(h0 + 0) * 32 + dq];
        float4 w1 = W4[(size_t)(h0 + 1) * 32 + dq];
        float4 w2 = W4[(size_t)(h0 + 2) * 32 + dq];
        float4 w3 = W4[(size_t)(h0 + 3) * 32 + dq];
        #pragma unroll
        for (int j = 0; j < 8; j++) {
            float4 lf = smem[j * 256 + hs * 32 + c];   // broadcast
            acc[j].x += lf.x * w0.x + lf.y * w1.x + lf.z * w2.x + lf.w * w3.x;
            acc[j].y += lf.x * w0.y + lf.y * w1.y + lf.z * w2.y + lf.w * w3.y;
            acc[j].z += lf.x * w0.z + lf.y * w1.z + lf.z * w2.z + lf.w * w3.z;
            acc[j].w += lf.x * w0.w + lf.y * w1.w + lf.z * w2.w + lf.w * w3.w;
        }
    }
    __syncthreads();

    #pragma unroll
    for (int j = 0; j < 8; j++) smem[hs * 256 + j * 32 + dq] = acc[j];
    __syncthreads();

    {
        const int j2  = tid >> 5;
        const int dq2 = tid & 31;
        float4 s = make_float4(0.f, 0.f, 0.f, 0.f);
        #pragma unroll
        for (int h = 0; h < 8; h++) {
            float4 v = smem[h * 256 + j2 * 32 + dq2];
            s.x += v.x; s.y += v.y; s.z += v.z; s.w += v.w;
        }
        float4 bb = bias4[dq2];
        s.x += bb.x; s.y += bb.y; s.z += bb.z; s.w += bb.w;
        out4[(size_t)(b0 + j2) * 32 + dq2] = s;
    }
}

// ---------------------------------------------------------------------------
// K2: logits = query @ key^T. 64x64 tile, 256 threads, 4x4 register block.
// ---------------------------------------------------------------------------
#define L_SMEM_BYTES (2 * 64 * 33 * (int)sizeof(float4))

__global__ __launch_bounds__(256, 1)
void logits_kernel(const float* __restrict__ key)
{
    extern __shared__ float4 dyn[];
    float4* qs = dyn;             // [64][33]
    float4* ks = dyn + 64 * 33;   // [64][33]

    const int b0 = blockIdx.x * 64;
    const int s0 = blockIdx.y * 64;
    const int tid = threadIdx.x;

    const float4* q4 = g_query;
    const float4* k4 = (const float4*)key;
    #pragma unroll
    for (int i = tid; i < 64 * 32; i += 256) {
        int r = i >> 5, c = i & 31;
        qs[r * 33 + c] = q4[(size_t)(b0 + r) * 32 + c];
        ks[r * 33 + c] = k4[(size_t)(s0 + r) * 32 + c];
    }
    __syncthreads();

    const int tx = tid & 15;
    const int ty = tid >> 4;

    float acc[4][4];
    #pragma unroll
    for (int i = 0; i < 4; i++)
        #pragma unroll
        for (int j = 0; j < 4; j++) acc[i][j] = 0.f;

    #pragma unroll 8
    for (int c = 0; c < 32; c++) {
        float4 qv[4], kv[4];
        #pragma unroll
        for (int i = 0; i < 4; i++) qv[i] = qs[(ty + 16 * i) * 33 + c];
        #pragma unroll
        for (int j = 0; j < 4; j++) kv[j] = ks[(tx + 16 * j) * 33 + c];
        #pragma unroll
        for (int i = 0; i < 4; i++)
            #pragma unroll
            for (int j = 0; j < 4; j++)
                acc[i][j] += qv[i].x * kv[j].x + qv[i].y * kv[j].y
                           + qv[i].z * kv[j].z + qv[i].w * kv[j].w;
    }

    #pragma unroll
    for (int i = 0; i < 4; i++)
        #pragma unroll
        for (int j = 0; j < 4; j++)
            g_logits[(size_t)(b0 + ty + 16 * i) * Sn + s0 + tx + 16 * j] = acc[i][j];
}

// ---------------------------------------------------------------------------
// K3: per-batch: top-32, softmax-32, weights row, read gather, gate; stash
// topk indices/weights for the fixup kernel.
// ---------------------------------------------------------------------------
__global__ __launch_bounds__(256, 4)
void batch_kernel(const float* __restrict__ latent,
                  const float* __restrict__ memory,
                  const float* __restrict__ wg, const float* __restrict__ bg,
                  const float* __restrict__ wd, const float* __restrict__ bd,
                  const float* __restrict__ wp, const float* __restrict__ bp,
                  float* __restrict__ out)
{
    __shared__ float sl[Sn];
    __shared__ int   ti[Kn];
    __shared__ float tw[Kn];
    __shared__ float rd[Dn];
    __shared__ float r3[24];

    const int b   = blockIdx.x;
    const int tid = threadIdx.x;

    for (int i = tid; i < Sn; i += 256) sl[i] = g_logits[(size_t)b * Sn + i];
    __syncthreads();

    if (tid < 32) {
        const int lane = tid;
        for (int it = 0; it < Kn; it++) {
            float bv = -1e30f; int bi = 0;
            #pragma unroll
            for (int j = 0; j < 32; j++) {
                float v = sl[lane + 32 * j];
                if (v > bv) { bv = v; bi = lane + 32 * j; }
            }
            #pragma unroll
            for (int o = 16; o; o >>= 1) {
                float ov = __shfl_xor_sync(0xffffffffu, bv, o);
                int   oi = __shfl_xor_sync(0xffffffffu, bi, o);
                if (ov > bv || (ov == bv && oi < bi)) { bv = ov; bi = oi; }
            }
            if ((bi & 31) == lane) sl[bi] = -1e30f;
            if (lane == 0) { ti[it] = bi; tw[it] = bv; }
            __syncwarp();
        }
        float m = tw[0];
        float e = __expf(tw[lane] - m);
        float s = e;
        #pragma unroll
        for (int o = 16; o; o >>= 1) s += __shfl_xor_sync(0xffffffffu, s, o);
        tw[lane] = e / s;
        g_ti[b * Kn + lane] = ti[lane];
        g_tw[b * Kn + lane] = e / s;
        __syncwarp();
    }
    __syncthreads();

    float* wout = out + W_OFF + (size_t)b * Sn;
    for (int i = tid; i < Sn; i += 256) wout[i] = 0.f;
    __syncthreads();
    if (tid < Kn) wout[ti[tid]] = tw[tid];

    if (tid < Dn) {
        float acc = 0.f;
        #pragma unroll 8
        for (int k = 0; k < Kn; k++)
            acc += tw[k] * memory[((size_t)b * Sn + ti[k]) * Dn + tid];
        out[READ_OFF + (size_t)b * Dn + tid] = acc;
        rd[tid] = acc;
    }
    __syncthreads();

    float pg = 0.f, pd = 0.f, pp = 0.f;
    const float* latb = latent + (size_t)b * Hn;
    for (int j = tid; j < Hn; j += 256) {
        float x = latb[j];
        pg += x * wg[j];
        pd += x * wd[j];
        pp += x * wp[j];
    }
    if (tid < Dn) {
        float x = rd[tid];
        pg += x * wg[Hn + tid];
        pd += x * wd[Hn + tid];
    }
    #pragma unroll
    for (int o = 16; o; o >>= 1) {
        pg += __shfl_xor_sync(0xffffffffu, pg, o);
        pd += __shfl_xor_sync(0xffffffffu, pd, o);
        pp += __shfl_xor_sync(0xffffffffu, pp, o);
    }
    const int wpid = tid >> 5, lane = tid & 31;
    if (lane == 0) { r3[wpid] = pg; r3[8 + wpid] = pd; r3[16 + wpid] = pp; }
    __syncthreads();
    if (tid == 0) {
        float G = 0.f, Dv = 0.f, P = 0.f;
        #pragma unroll
        for (int i = 0; i < 8; i++) { G += r3[i]; Dv += r3[8 + i]; P += r3[16 + i]; }
        float gate = 1.f / (1.f + __expf(-(G + bg[0])));
        float dmd  = tanhf(Dv + bd[0]);
        gate = gate * (0.75f + 0.5f * (dmd + 1.0f) * 0.5f);
        gate = fminf(fmaxf(gate, 0.f), 1.f);
        float ph = P + bp[0];
        gate *= 0.5f * (1.f + cosf(ph));
        g_gate[b] = gate;
    }
}

// ---------------------------------------------------------------------------
// K0 (concurrent stream): pure 256 MB streaming copy memory -> out. No data
// dependency on the prologue, so it overlaps with K1/K2/K3 entirely.
// ---------------------------------------------------------------------------
__global__ __launch_bounds__(256, 8)
void pure_copy_kernel(const float4* __restrict__ src, float4* __restrict__ dst)
{
    size_t base = (size_t)blockIdx.x * 1024 + threadIdx.x;
    #pragma unroll
    for (int j = 0; j < 4; j++) {
        size_t g = base + (size_t)j * 256;
        __stcs(&dst[g], __ldcs(&src[g]));
    }
}

// ---------------------------------------------------------------------------
// K5 (after join): blend the 32 top-k rows per batch.
// Block = one batch; 32 rows x 32 float4 = 1024 quads; thread does 4.
// Warp i covers one full row per iteration -> fully coalesced 512B segments.
// ---------------------------------------------------------------------------
__global__ __launch_bounds__(256, 8)
void fixup_kernel(const float4* __restrict__ mem4, float* __restrict__ out)
{
    __shared__ int   ti[Kn];
    __shared__ float gw[Kn];

    const int b   = blockIdx.x;
    const int tid = threadIdx.x;

    if (tid < Kn) {
        ti[tid] = g_ti[b * Kn + tid];
        gw[tid] = g_gate[b] * g_tw[b * Kn + tid];
    }
    __syncthreads();

    float4* dst = (float4*)(out + MEM_OFF);

    #pragma unroll
    for (int i = 0; i < 4; i++) {
        int idx = tid + i * 256;          // 0..1023
        int r   = idx >> 5;               // topk slot 0..31
        int q   = idx & 31;               // quad in row
        int s   = ti[r];
        float w = gw[r];
        size_t g = ((size_t)b * Sn + s) * 32 + q;
        float4 m = mem4[g];
        float4 v = g_value[b * 32 + q];
        m.x += w * (v.x - m.x);
        m.y += w * (v.y - m.y);
        m.z += w * (v.z - m.z);
        m.w += w * (v.w - m.w);
        dst[g] = m;
    }
}

// ---------------------------------------------------------------------------
extern "C" void kernel_launch(void* const* d_in, const int* in_sizes, int n_in,
                              void* d_out, int out_size)
{
    const float* latent    = (const float*)d_in[0];
    const float* memory    = (const float*)d_in[1];
    const float* rq_w      = (const float*)d_in[2];
    const float* rq_b      = (const float*)d_in[3];
    const float* mem_key   = (const float*)d_in[4];
    const float* wg_w      = (const float*)d_in[5];
    const float* wg_b      = (const float*)d_in[6];
    const float* wd_w      = (const float*)d_in[7];
    const float* wd_b      = (const float*)d_in[8];
    const float* wp_w      = (const float*)d_in[9];
    const float* wp_b      = (const float*)d_in[10];
    const float* wv_w      = (const float*)d_in[11];
    const float* wv_b      = (const float*)d_in[12];
    float* out = (float*)d_out;

    // One-time infra (created on the first, non-captured call; identical work
    // graph every call thereafter).
    static cudaStream_t s_copy = nullptr;
    static cudaEvent_t  ev_fork = nullptr, ev_join = nullptr;
    if (s_copy == nullptr) {
        cudaStreamCreateWithFlags(&s_copy, cudaStreamNonBlocking);
        cudaEventCreateWithFlags(&ev_fork, cudaEventDisableTiming);
        cudaEventCreateWithFlags(&ev_join, cudaEventDisableTiming);
        cudaFuncSetAttribute(logits_kernel,
                             cudaFuncAttributeMaxDynamicSharedMemorySize,
                             L_SMEM_BYTES);
    }

    // Fork: big copy runs concurrently with the prologue.
    cudaEventRecord(ev_fork, 0);
    cudaStreamWaitEvent(s_copy, ev_fork, 0);
    pure_copy_kernel<<<(Bn * Sn * Dn / 4) / 1024, 256, 0, s_copy>>>(
        (const float4*)memory, (float4*)(out + MEM_OFF));
    cudaEventRecord(ev_join, s_copy);

    // Prologue on the capture stream.
    qv_kernel<<<dim3(Bn / 8, 2), 256>>>(latent, rq_w, rq_b, wv_w, wv_b);
    logits_kernel<<<dim3(Bn / 64, Sn / 64), 256, L_SMEM_BYTES>>>(mem_key);
    batch_kernel<<<Bn, 256>>>(latent, memory,
                              wg_w, wg_b, wd_w, wd_b, wp_w, wp_b, out);

    // Join, then blend the 16K touched rows.
    cudaStreamWaitEvent(0, ev_join, 0);
    fixup_kernel<<<Bn, 256>>>((const float4*)memory, out);
}

// round 4
// speedup vs baseline: 1.0085x; 1.0085x over previous
#include <cuda_runtime.h>
#include <math.h>

#define Bn 512
#define Hn 1024
#define Sn 1024
#define Dn 128
#define Kn 32

// Output layout: [read (B*D)] [new_memory (B*S*D)] [weights (B*S)]
#define READ_OFF 0
#define MEM_OFF  (Bn*Dn)
#define W_OFF    (Bn*Dn + (size_t)Bn*Sn*Dn)

// Scratch (no allocation allowed -> device globals)
__device__ float4 g_query[Bn * (Dn/4)];   // [B][32] float4
__device__ float4 g_value[Bn * (Dn/4)];
__device__ float  g_logits[Bn * Sn];
__device__ float  g_gate[Bn];
__device__ int    g_ti[Bn * Kn];
__device__ float  g_tw[Bn * Kn];

// ---------------------------------------------------------------------------
// K1: query = latent @ Wq + bq ; value = latent @ Wv + bv
// ---------------------------------------------------------------------------
__global__ __launch_bounds__(256, 2)
void qv_kernel(const float* __restrict__ latent,
               const float* __restrict__ Wq, const float* __restrict__ bq,
               const float* __restrict__ Wv, const float* __restrict__ bv)
{
    __shared__ float4 smem[8 * 256];   // 32 KB: latent tile, then reduction overlay

    const int b0 = blockIdx.x * 8;
    const float4* W4    = (const float4*)(blockIdx.y ? Wv : Wq);
    const float4* bias4 = (const float4*)(blockIdx.y ? bv : bq);
    float4*       out4  = blockIdx.y ? g_value : g_query;

    const int tid = threadIdx.x;
    const int dq  = tid & 31;
    const int hs  = tid >> 5;

    {
        const float4* src = (const float4*)(latent + (size_t)b0 * Hn);
        #pragma unroll
        for (int i = 0; i < 8; i++) smem[tid + i * 256] = src[tid + i * 256];
    }
    __syncthreads();

    float4 acc[8];
    #pragma unroll
    for (int j = 0; j < 8; j++) acc[j] = make_float4(0.f, 0.f, 0.f, 0.f);

    const int hbase = hs * 128;
    #pragma unroll 4
    for (int c = 0; c < 32; c++) {
        const int h0 = hbase + c * 4;
        float4 w0 = W4[(size_t)(h0 + 0) * 32 + dq];
        float4 w1 = W4[(size_t)(h0 + 1) * 32 + dq];
        float4 w2 = W4[(size_t)(h0 + 2) * 32 + dq];
        float4 w3 = W4[(size_t)(h0 + 3) * 32 + dq];
        #pragma unroll
        for (int j = 0; j < 8; j++) {
            float4 lf = smem[j * 256 + hs * 32 + c];   // broadcast
            acc[j].x += lf.x * w0.x + lf.y * w1.x + lf.z * w2.x + lf.w * w3.x;
            acc[j].y += lf.x * w0.y + lf.y * w1.y + lf.z * w2.y + lf.w * w3.y;
            acc[j].z += lf.x * w0.z + lf.y * w1.z + lf.z * w2.z + lf.w * w3.z;
            acc[j].w += lf.x * w0.w + lf.y * w1.w + lf.z * w2.w + lf.w * w3.w;
        }
    }
    __syncthreads();

    #pragma unroll
    for (int j = 0; j < 8; j++) smem[hs * 256 + j * 32 + dq] = acc[j];
    __syncthreads();

    {
        const int j2  = tid >> 5;
        const int dq2 = tid & 31;
        float4 s = make_float4(0.f, 0.f, 0.f, 0.f);
        #pragma unroll
        for (int h = 0; h < 8; h++) {
            float4 v = smem[h * 256 + j2 * 32 + dq2];
            s.x += v.x; s.y += v.y; s.z += v.z; s.w += v.w;
        }
        float4 bb = bias4[dq2];
        s.x += bb.x; s.y += bb.y; s.z += bb.z; s.w += bb.w;
        out4[(size_t)(b0 + j2) * 32 + dq2] = s;
    }
}

// ---------------------------------------------------------------------------
// K2: logits = query @ key^T. 64x64 tile, 256 threads, 4x4 register block.
// ---------------------------------------------------------------------------
#define L_SMEM_BYTES (2 * 64 * 33 * (int)sizeof(float4))

__global__ __launch_bounds__(256, 1)
void logits_kernel(const float* __restrict__ key)
{
    extern __shared__ float4 dyn[];
    float4* qs = dyn;             // [64][33]
    float4* ks = dyn + 64 * 33;   // [64][33]

    const int b0 = blockIdx.x * 64;
    const int s0 = blockIdx.y * 64;
    const int tid = threadIdx.x;

    const float4* q4 = g_query;
    const float4* k4 = (const float4*)key;
    #pragma unroll
    for (int i = tid; i < 64 * 32; i += 256) {
        int r = i >> 5, c = i & 31;
        qs[r * 33 + c] = q4[(size_t)(b0 + r) * 32 + c];
        ks[r * 33 + c] = k4[(size_t)(s0 + r) * 32 + c];
    }
    __syncthreads();

    const int tx = tid & 15;
    const int ty = tid >> 4;

    float acc[4][4];
    #pragma unroll
    for (int i = 0; i < 4; i++)
        #pragma unroll
        for (int j = 0; j < 4; j++) acc[i][j] = 0.f;

    #pragma unroll 8
    for (int c = 0; c < 32; c++) {
        float4 qv[4], kv[4];
        #pragma unroll
        for (int i = 0; i < 4; i++) qv[i] = qs[(ty + 16 * i) * 33 + c];
        #pragma unroll
        for (int j = 0; j < 4; j++) kv[j] = ks[(tx + 16 * j) * 33 + c];
        #pragma unroll
        for (int i = 0; i < 4; i++)
            #pragma unroll
            for (int j = 0; j < 4; j++)
                acc[i][j] += qv[i].x * kv[j].x + qv[i].y * kv[j].y
                           + qv[i].z * kv[j].z + qv[i].w * kv[j].w;
    }

    #pragma unroll
    for (int i = 0; i < 4; i++)
        #pragma unroll
        for (int j = 0; j < 4; j++)
            g_logits[(size_t)(b0 + ty + 16 * i) * Sn + s0 + tx + 16 * j] = acc[i][j];
}

// ---------------------------------------------------------------------------
// K3: per-batch: top-32, softmax-32, read gather, gate. Weights-row zero and
// scatter moved to the copy/fixup branch (off this critical path).
// ---------------------------------------------------------------------------
__global__ __launch_bounds__(256, 4)
void batch_kernel(const float* __restrict__ latent,
                  const float* __restrict__ memory,
                  const float* __restrict__ wg, const float* __restrict__ bg,
                  const float* __restrict__ wd, const float* __restrict__ bd,
                  const float* __restrict__ wp, const float* __restrict__ bp,
                  float* __restrict__ out)
{
    __shared__ float sl[Sn];
    __shared__ int   ti[Kn];
    __shared__ float tw[Kn];
    __shared__ float rd[Dn];
    __shared__ float r3[24];

    const int b   = blockIdx.x;
    const int tid = threadIdx.x;

    for (int i = tid; i < Sn; i += 256) sl[i] = g_logits[(size_t)b * Sn + i];
    __syncthreads();

    if (tid < 32) {
        const int lane = tid;
        for (int it = 0; it < Kn; it++) {
            float bv = -1e30f; int bi = 0;
            #pragma unroll
            for (int j = 0; j < 32; j++) {
                float v = sl[lane + 32 * j];
                if (v > bv) { bv = v; bi = lane + 32 * j; }
            }
            #pragma unroll
            for (int o = 16; o; o >>= 1) {
                float ov = __shfl_xor_sync(0xffffffffu, bv, o);
                int   oi = __shfl_xor_sync(0xffffffffu, bi, o);
                if (ov > bv || (ov == bv && oi < bi)) { bv = ov; bi = oi; }
            }
            if ((bi & 31) == lane) sl[bi] = -1e30f;
            if (lane == 0) { ti[it] = bi; tw[it] = bv; }
            __syncwarp();
        }
        float m = tw[0];
        float e = __expf(tw[lane] - m);
        float s = e;
        #pragma unroll
        for (int o = 16; o; o >>= 1) s += __shfl_xor_sync(0xffffffffu, s, o);
        float wgt = e / s;
        tw[lane] = wgt;
        g_ti[b * Kn + lane] = ti[lane];
        g_tw[b * Kn + lane] = wgt;
        __syncwarp();
    }
    __syncthreads();

    if (tid < Dn) {
        float acc = 0.f;
        #pragma unroll 8
        for (int k = 0; k < Kn; k++)
            acc += tw[k] * memory[((size_t)b * Sn + ti[k]) * Dn + tid];
        out[READ_OFF + (size_t)b * Dn + tid] = acc;
        rd[tid] = acc;
    }
    __syncthreads();

    float pg = 0.f, pd = 0.f, pp = 0.f;
    const float* latb = latent + (size_t)b * Hn;
    for (int j = tid; j < Hn; j += 256) {
        float x = latb[j];
        pg += x * wg[j];
        pd += x * wd[j];
        pp += x * wp[j];
    }
    if (tid < Dn) {
        float x = rd[tid];
        pg += x * wg[Hn + tid];
        pd += x * wd[Hn + tid];
    }
    #pragma unroll
    for (int o = 16; o; o >>= 1) {
        pg += __shfl_xor_sync(0xffffffffu, pg, o);
        pd += __shfl_xor_sync(0xffffffffu, pd, o);
        pp += __shfl_xor_sync(0xffffffffu, pp, o);
    }
    const int wpid = tid >> 5, lane = tid & 31;
    if (lane == 0) { r3[wpid] = pg; r3[8 + wpid] = pd; r3[16 + wpid] = pp; }
    __syncthreads();
    if (tid == 0) {
        float G = 0.f, Dv = 0.f, P = 0.f;
        #pragma unroll
        for (int i = 0; i < 8; i++) { G += r3[i]; Dv += r3[8 + i]; P += r3[16 + i]; }
        float gate = 1.f / (1.f + __expf(-(G + bg[0])));
        float dmd  = tanhf(Dv + bd[0]);
        gate = gate * (0.75f + 0.5f * (dmd + 1.0f) * 0.5f);
        gate = fminf(fmaxf(gate, 0.f), 1.f);
        float ph = P + bp[0];
        gate *= 0.5f * (1.f + cosf(ph));
        g_gate[b] = gate;
    }
}

// ---------------------------------------------------------------------------
// K0 (low-priority stream): 256 MB streaming copy memory -> out, plus
// zero-fill of the 2 MB weights region (blocks >= NCOPY).
// ---------------------------------------------------------------------------
#define NCOPY (Bn * Sn * Dn / 4 / 1024)        // 16384 copy blocks
#define NZERO (Bn * Sn / 4 / 1024)             // 128 zero blocks

__global__ __launch_bounds__(256, 8)
void pure_copy_kernel(const float4* __restrict__ src, float* __restrict__ out)
{
    if (blockIdx.x < NCOPY) {
        float4* dst = (float4*)(out + MEM_OFF);
        size_t base = (size_t)blockIdx.x * 1024 + threadIdx.x;
        #pragma unroll
        for (int j = 0; j < 4; j++) {
            size_t g = base + (size_t)j * 256;
            __stcs(&dst[g], __ldcs(&src[g]));
        }
    } else {
        float4* wz = (float4*)(out + W_OFF);
        size_t base = (size_t)(blockIdx.x - NCOPY) * 1024 + threadIdx.x;
        float4 z = make_float4(0.f, 0.f, 0.f, 0.f);
        #pragma unroll
        for (int j = 0; j < 4; j++)
            __stcs(&wz[base + (size_t)j * 256], z);
    }
}

// ---------------------------------------------------------------------------
// K5 (after join): blend 32 top-k rows per batch + scatter weights.
// ---------------------------------------------------------------------------
__global__ __launch_bounds__(256, 8)
void fixup_kernel(const float4* __restrict__ mem4, float* __restrict__ out)
{
    __shared__ int   ti[Kn];
    __shared__ float gw[Kn];

    const int b   = blockIdx.x;
    const int tid = threadIdx.x;

    if (tid < Kn) {
        int   idx = g_ti[b * Kn + tid];
        float w   = g_tw[b * Kn + tid];
        ti[tid] = idx;
        gw[tid] = g_gate[b] * w;
        out[W_OFF + (size_t)b * Sn + idx] = w;   // weight scatter
    }
    __syncthreads();

    float4* dst = (float4*)(out + MEM_OFF);

    #pragma unroll
    for (int i = 0; i < 4; i++) {
        int idx = tid + i * 256;          // 0..1023
        int r   = idx >> 5;               // topk slot
        int q   = idx & 31;               // quad in row
        int s   = ti[r];
        float w = gw[r];
        size_t g = ((size_t)b * Sn + s) * 32 + q;
        float4 m = mem4[g];
        float4 v = g_value[b * 32 + q];
        m.x += w * (v.x - m.x);
        m.y += w * (v.y - m.y);
        m.z += w * (v.z - m.z);
        m.w += w * (v.w - m.w);
        dst[g] = m;
    }
}

// ---------------------------------------------------------------------------
extern "C" void kernel_launch(void* const* d_in, const int* in_sizes, int n_in,
                              void* d_out, int out_size)
{
    const float* latent    = (const float*)d_in[0];
    const float* memory    = (const float*)d_in[1];
    const float* rq_w      = (const float*)d_in[2];
    const float* rq_b      = (const float*)d_in[3];
    const float* mem_key   = (const float*)d_in[4];
    const float* wg_w      = (const float*)d_in[5];
    const float* wg_b      = (const float*)d_in[6];
    const float* wd_w      = (const float*)d_in[7];
    const float* wd_b      = (const float*)d_in[8];
    const float* wp_w      = (const float*)d_in[9];
    const float* wp_b      = (const float*)d_in[10];
    const float* wv_w      = (const float*)d_in[11];
    const float* wv_b      = (const float*)d_in[12];
    float* out = (float*)d_out;

    static cudaStream_t s_copy = nullptr;
    static cudaEvent_t  ev_fork = nullptr, ev_join = nullptr;
    if (s_copy == nullptr) {
        int lo, hi;
        cudaDeviceGetStreamPriorityRange(&lo, &hi);   // lo = least priority
        cudaStreamCreateWithPriority(&s_copy, cudaStreamNonBlocking, lo);
        cudaEventCreateWithFlags(&ev_fork, cudaEventDisableTiming);
        cudaEventCreateWithFlags(&ev_join, cudaEventDisableTiming);
        cudaFuncSetAttribute(logits_kernel,
                             cudaFuncAttributeMaxDynamicSharedMemorySize,
                             L_SMEM_BYTES);
    }

    cudaEventRecord(ev_fork, 0);
    cudaStreamWaitEvent(s_copy, ev_fork, 0);

    // Prologue first (high-priority default stream) so its CTAs win slots.
    qv_kernel<<<dim3(Bn / 8, 2), 256>>>(latent, rq_w, rq_b, wv_w, wv_b);
    logits_kernel<<<dim3(Bn / 64, Sn / 64), 256, L_SMEM_BYTES>>>(mem_key);
    batch_kernel<<<Bn, 256>>>(latent, memory,
                              wg_w, wg_b, wd_w, wd_b, wp_w, wp_b, out);

    // Big copy on the low-priority stream, concurrent with the prologue.
    pure_copy_kernel<<<NCOPY + NZERO, 256, 0, s_copy>>>(
        (const float4*)memory, out);
    cudaEventRecord(ev_join, s_copy);

    // Join, then blend the 16K touched rows + weight scatter.
    cudaStreamWaitEvent(0, ev_join, 0);
    fixup_kernel<<<Bn, 256>>>((const float4*)memory, out);
}